// round 16
// baseline (speedup 1.0000x reference)
#include <cuda_runtime.h>
#include <cuda_bf16.h>
#include <cstdint>

// Problem constants
#define B_  64
#define H_  128
#define W_  128
#define C_  3
#define KH_ 5
#define KW_ 5
#define N_  10
#define PAD_ 2
#define HW_ (H_ * W_)

#define RPB_ 4      // output rows per block
#define FR_  8      // pair-array rows: h0-2 .. h0+5
#define NP_  66     // pair entries per (c,row)

typedef unsigned long long u64;

__device__ __forceinline__ u64 pk2(float lo, float hi) {
    u64 r;
    asm("mov.b64 %0, {%1, %2};" : "=l"(r) : "f"(lo), "f"(hi));
    return r;
}
__device__ __forceinline__ u64 ffma2(u64 a, u64 b, u64 c) {
    u64 d;
    asm("fma.rn.f32x2 %0, %1, %2, %3;" : "=l"(d) : "l"(a), "l"(b), "l"(c));
    return d;
}
__device__ __forceinline__ uint32_t smem_u32(const void* p) {
    uint32_t a;
    asm("{ .reg .u64 t; cvta.to.shared.u64 t, %1; cvt.u32.u64 %0, t; }" : "=r"(a) : "l"(p));
    return a;
}
__device__ __forceinline__ void cp_async16(uint32_t dst, const void* src) {
    asm volatile("cp.async.cg.shared.global [%0], [%1], 16;" :: "r"(dst), "l"(src) : "memory");
}

// R13 dataflow (pixel-pair f32x2, dual-phase pair arrays, dup weights) with an
// EXPLICIT 1-tap software pipeline: while the 30 FFMA2s of tap t issue
// (~60 cyc), the 8 operand loads of tap t+1 are in flight. Requires occupancy
// 2 (128-reg cap): 60 acc + 12 iv + 40 wt double-buffer regs. In-thread
// latency coverage replaces warp-count coverage.
extern "C" __global__ void __launch_bounds__(256, 2)
cdna_apply_kernel(const float* __restrict__ images,
                  const float* __restrict__ kernels,
                  float* __restrict__ out) {
    const int b  = blockIdx.y;          // batch
    const int h0 = blockIdx.x * RPB_;   // first of 4 output rows

    __shared__ __align__(16) float s_row[FR_][404];    // scratch, col x at 8+3x+c
    __shared__ __align__(16) u64 s_p0[C_][FR_][NP_];   // pair phase 0
    __shared__ __align__(16) u64 s_p1[C_][FR_][NP_];   // pair phase 1
    __shared__ __align__(16) u64 s_kd[25][10];         // dup weights

    const int tid = threadIdx.x;
    const float* img = images  + (size_t)b * (H_ * W_ * C_);
    const float* ker = kernels + b * (KH_ * KW_ * N_);

    // --- zero scratch ---
    {
        float4* p = reinterpret_cast<float4*>(&s_row[0][0]);
        for (int i = tid; i < (FR_ * 404) / 4; i += 256)
            p[i] = make_float4(0.f, 0.f, 0.f, 0.f);
    }
    if (tid < 250) {
        const int tap = tid / 10;
        const int n   = tid - tap * 10;
        const float v = ker[tid];
        s_kd[tap][n] = pk2(v, v);
    }
    __syncthreads();

    // --- interior fill via cp.async: 8 rows x 96 float4 ---
    for (int i = tid; i < FR_ * 96; i += 256) {
        const int r    = i / 96;
        const int col4 = i - r * 96;
        const int gr   = h0 - 2 + r;
        if ((unsigned)gr < (unsigned)H_) {
            const uint32_t dst = smem_u32(&s_row[r][8 + col4 * 4]);
            cp_async16(dst, img + gr * (W_ * C_) + col4 * 4);
        }
    }
    asm volatile("cp.async.commit_group;" ::: "memory");
    asm volatile("cp.async.wait_group 0;" ::: "memory");
    __syncthreads();

    // --- rearrange into dual-phase pair arrays ---
    for (int idx = tid; idx < C_ * FR_ * NP_; idx += 256) {
        const int c   = idx / (FR_ * NP_);
        const int rem = idx - c * (FR_ * NP_);
        const int r   = rem / NP_;
        const int jj  = rem - r * NP_;
        const float* sr = &s_row[r][8 + c];
        const float va = sr[3 * (2 * jj - 2)];
        const float vb = sr[3 * (2 * jj - 1)];
        const float vc = sr[3 * (2 * jj)];
        s_p0[c][r][jj] = pk2(va, vb);
        s_p1[c][r][jj] = pk2(vb, vc);
    }
    __syncthreads();

    const int p  = tid & 63;    // pair index; pixels w0=2p, w0+1
    const int hr = tid >> 6;    // row within block (0..3)

    u64 acc[N_][C_];
#pragma unroll
    for (int n = 0; n < N_; ++n)
#pragma unroll
        for (int c = 0; c < C_; ++c) acc[n][c] = 0ull;

    // tap t: dh=t/5, dw=t%5; phase = dw&1, j = p + (dw>>1)
    // double buffers
    u64        iv[2][3];
    ulonglong2 kw[2][5];

#define LOAD_TAP(buf, T)                                                        \
    do {                                                                        \
        constexpr int dh_ = (T) / 5, dw_ = (T) % 5;                             \
        const int ro_ = (hr + dh_) * NP_ + p + (dw_ >> 1);                      \
        const u64* ph_ = (dw_ & 1) ? &s_p1[0][0][0] : &s_p0[0][0][0];           \
        iv[buf][0] = ph_[0 * (FR_ * NP_) + ro_];                                \
        iv[buf][1] = ph_[1 * (FR_ * NP_) + ro_];                                \
        iv[buf][2] = ph_[2 * (FR_ * NP_) + ro_];                                \
        const u64* kt_ = &s_kd[T][0];                                           \
        kw[buf][0] = *reinterpret_cast<const ulonglong2*>(kt_);                 \
        kw[buf][1] = *reinterpret_cast<const ulonglong2*>(kt_ + 2);             \
        kw[buf][2] = *reinterpret_cast<const ulonglong2*>(kt_ + 4);             \
        kw[buf][3] = *reinterpret_cast<const ulonglong2*>(kt_ + 6);             \
        kw[buf][4] = *reinterpret_cast<const ulonglong2*>(kt_ + 8);             \
    } while (0)

    LOAD_TAP(0, 0);

#pragma unroll
    for (int t = 0; t < 25; ++t) {
        const int cur = t & 1;
        const int nxt = cur ^ 1;
        if (t < 24) {
            switch (t + 1) {   // compile-time constant per unrolled iteration
#define CASE_LT(TT) case TT: LOAD_TAP(nxt, TT); break;
                CASE_LT(1)  CASE_LT(2)  CASE_LT(3)  CASE_LT(4)  CASE_LT(5)
                CASE_LT(6)  CASE_LT(7)  CASE_LT(8)  CASE_LT(9)  CASE_LT(10)
                CASE_LT(11) CASE_LT(12) CASE_LT(13) CASE_LT(14) CASE_LT(15)
                CASE_LT(16) CASE_LT(17) CASE_LT(18) CASE_LT(19) CASE_LT(20)
                CASE_LT(21) CASE_LT(22) CASE_LT(23) CASE_LT(24)
#undef CASE_LT
            }
        }
        const u64 i0 = iv[cur][0], i1 = iv[cur][1], i2 = iv[cur][2];
        const ulonglong2 k01 = kw[cur][0], k23 = kw[cur][1], k45 = kw[cur][2],
                         k67 = kw[cur][3], k89 = kw[cur][4];

        acc[0][0] = ffma2(i0, k01.x, acc[0][0]);
        acc[0][1] = ffma2(i1, k01.x, acc[0][1]);
        acc[0][2] = ffma2(i2, k01.x, acc[0][2]);
        acc[1][0] = ffma2(i0, k01.y, acc[1][0]);
        acc[1][1] = ffma2(i1, k01.y, acc[1][1]);
        acc[1][2] = ffma2(i2, k01.y, acc[1][2]);
        acc[2][0] = ffma2(i0, k23.x, acc[2][0]);
        acc[2][1] = ffma2(i1, k23.x, acc[2][1]);
        acc[2][2] = ffma2(i2, k23.x, acc[2][2]);
        acc[3][0] = ffma2(i0, k23.y, acc[3][0]);
        acc[3][1] = ffma2(i1, k23.y, acc[3][1]);
        acc[3][2] = ffma2(i2, k23.y, acc[3][2]);
        acc[4][0] = ffma2(i0, k45.x, acc[4][0]);
        acc[4][1] = ffma2(i1, k45.x, acc[4][1]);
        acc[4][2] = ffma2(i2, k45.x, acc[4][2]);
        acc[5][0] = ffma2(i0, k45.y, acc[5][0]);
        acc[5][1] = ffma2(i1, k45.y, acc[5][1]);
        acc[5][2] = ffma2(i2, k45.y, acc[5][2]);
        acc[6][0] = ffma2(i0, k67.x, acc[6][0]);
        acc[6][1] = ffma2(i1, k67.x, acc[6][1]);
        acc[6][2] = ffma2(i2, k67.x, acc[6][2]);
        acc[7][0] = ffma2(i0, k67.y, acc[7][0]);
        acc[7][1] = ffma2(i1, k67.y, acc[7][1]);
        acc[7][2] = ffma2(i2, k67.y, acc[7][2]);
        acc[8][0] = ffma2(i0, k89.x, acc[8][0]);
        acc[8][1] = ffma2(i1, k89.x, acc[8][1]);
        acc[8][2] = ffma2(i2, k89.x, acc[8][2]);
        acc[9][0] = ffma2(i0, k89.y, acc[9][0]);
        acc[9][1] = ffma2(i1, k89.y, acc[9][1]);
        acc[9][2] = ffma2(i2, k89.y, acc[9][2]);
    }
#undef LOAD_TAP

    // --- store: out[n][b][c][h][w0..w0+1] -> STG.64, coalesced ---
    const int hpix = h0 + hr;
    const int w0   = 2 * p;
    char* o0 = reinterpret_cast<char*>(out)
             + (((size_t)b * C_) * HW_ + hpix * W_ + w0) * sizeof(float);
#pragma unroll
    for (int n = 0; n < N_; ++n) {
        char* on = o0 + (size_t)n * (B_ * C_ * HW_) * sizeof(float);
#pragma unroll
        for (int c = 0; c < C_; ++c)
            *reinterpret_cast<u64*>(on + (size_t)c * HW_ * sizeof(float)) = acc[n][c];
    }
}

extern "C" void kernel_launch(void* const* d_in, const int* in_sizes, int n_in,
                              void* d_out, int out_size) {
    const float* images  = (const float*)d_in[0];  // [64,128,128,3]
    const float* kernels = (const float*)d_in[1];  // [64,5,5,10]
    float* out = (float*)d_out;                    // [10,64,3,128,128]
    (void)in_sizes; (void)n_in; (void)out_size;

    dim3 grid(H_ / RPB_, B_);   // 32 x 64 blocks
    dim3 block(256);
    cdna_apply_kernel<<<grid, block>>>(images, kernels, out);
}